// round 1
// baseline (speedup 1.0000x reference)
#include <cuda_runtime.h>
#include <cuda_bf16.h>
#include <cstdint>

// Problem constants (match reference_code)
#define NN 50000      // nodes
#define EE 800000     // edges
#define IN_F 128
#define DD 64
#define HH 4
#define HD 256        // H*D
#define LNUM 3
#define NEG_SLOPE 0.2f

// ---------------------------------------------------------------------------
// Scratch (static __device__ arrays — no allocation allowed)
// ---------------------------------------------------------------------------
__device__ float g_feat[(size_t)NN * HD];   // per-layer projected features [N,256]
__device__ float g_h[(size_t)NN * HD];      // layer io buffer (64 or 256 wide)
__device__ float g_el[(size_t)NN * HH];
__device__ float g_er[(size_t)NN * HH];
__device__ int   g_rowptr[NN + 1];
__device__ int   g_cur[NN];                 // histogram / scatter cursor
__device__ int   g_csr[EE];                 // src node per CSR slot (sorted by dst)

// ---------------------------------------------------------------------------
// CSR build: zero -> histogram(dst) -> scan -> scatter
// ---------------------------------------------------------------------------
__global__ void zero_cur_k() {
    int i = blockIdx.x * blockDim.x + threadIdx.x;
    if (i < NN) g_cur[i] = 0;
}

__global__ void hist_k(const int* __restrict__ dst) {
    int e = blockIdx.x * blockDim.x + threadIdx.x;
    if (e < EE) atomicAdd(&g_cur[dst[e]], 1);
}

// single-block exclusive scan over g_cur -> g_rowptr; also re-zeros g_cur
__global__ void scan_k() {
    __shared__ int ws[32];
    __shared__ int s_carry;
    int t = threadIdx.x, lane = t & 31, wid = t >> 5;
    if (t == 0) s_carry = 0;
    __syncthreads();
    for (int base = 0; base < NN; base += 1024) {
        int i = base + t;
        int v = (i < NN) ? g_cur[i] : 0;
        if (i < NN) g_cur[i] = 0;
        int x = v;
        #pragma unroll
        for (int o = 1; o < 32; o <<= 1) {
            int y = __shfl_up_sync(0xffffffffu, x, o);
            if (lane >= o) x += y;
        }
        if (lane == 31) ws[wid] = x;
        __syncthreads();
        if (wid == 0) {
            int y = ws[lane];
            #pragma unroll
            for (int o = 1; o < 32; o <<= 1) {
                int z = __shfl_up_sync(0xffffffffu, y, o);
                if (lane >= o) y += z;
            }
            ws[lane] = y;
        }
        __syncthreads();
        int incl = x + (wid ? ws[wid - 1] : 0);
        int carry = s_carry;
        if (i < NN) g_rowptr[i] = carry + incl - v;
        int total = ws[31];
        __syncthreads();
        if (t == 0) s_carry = carry + total;
        __syncthreads();
    }
    if (t == 0) g_rowptr[NN] = s_carry;
}

__global__ void scatter_k(const int* __restrict__ src, const int* __restrict__ dst) {
    int e = blockIdx.x * blockDim.x + threadIdx.x;
    if (e < EE) {
        int d = dst[e];
        int pos = g_rowptr[d] + atomicAdd(&g_cur[d], 1);
        g_csr[pos] = src[e];
    }
}

// ---------------------------------------------------------------------------
// GEMM + attention coefficients: feat = h @ W  ([N,K]@[K,256]); el/er = feat . al/ar
// 8 nodes per block, 256 threads, W stays L1/L2-resident.
// ---------------------------------------------------------------------------
template <int K>
__global__ void __launch_bounds__(256) gemm_attn_k(
    const float* __restrict__ hin, const float* __restrict__ W,
    const float* __restrict__ al, const float* __restrict__ ar)
{
    constexpr int NB = 8;
    __shared__ float sh[NB * K];
    __shared__ float red[8][2];
    int t = threadIdx.x, lane = t & 31, wid = t >> 5;
    int n0 = blockIdx.x * NB;

    for (int idx = t; idx < NB * K; idx += 256)
        sh[idx] = hin[(size_t)n0 * K + idx];
    __syncthreads();

    float acc[NB];
    #pragma unroll
    for (int i = 0; i < NB; i++) acc[i] = 0.f;

    float a_l = al[t], a_r = ar[t];

    for (int k = 0; k < K; k++) {
        float wv = __ldg(&W[k * HD + t]);
        #pragma unroll
        for (int i = 0; i < NB; i++) acc[i] += sh[i * K + k] * wv;
    }

    #pragma unroll
    for (int i = 0; i < NB; i++)
        g_feat[(size_t)(n0 + i) * HD + t] = acc[i];

    // per-node el/er reduction: 64-thread groups (one head = 2 warps)
    for (int i = 0; i < NB; i++) {
        float pl = acc[i] * a_l;
        float pr = acc[i] * a_r;
        #pragma unroll
        for (int o = 16; o; o >>= 1) {
            pl += __shfl_down_sync(0xffffffffu, pl, o);
            pr += __shfl_down_sync(0xffffffffu, pr, o);
        }
        if (lane == 0) { red[wid][0] = pl; red[wid][1] = pr; }
        __syncthreads();
        if (t < HH) {
            g_el[(n0 + i) * HH + t] = red[2 * t][0] + red[2 * t + 1][0];
            g_er[(n0 + i) * HH + t] = red[2 * t][1] + red[2 * t + 1][1];
        }
        __syncthreads();
    }
}

// ---------------------------------------------------------------------------
// Edge softmax + weighted aggregation. One block (128 thr) per dst node,
// warp h handles head h. CSR gather — no atomics.
// MEAN=true : write mean over heads + mean(bias) -> out[N,64]
// MEAN=false: write full [N,256] + bias
// ---------------------------------------------------------------------------
template <bool MEAN>
__global__ void __launch_bounds__(128) edge_agg_k(
    const float* __restrict__ b, float* __restrict__ out)
{
    constexpr int MAXDEG = 512;
    int n = blockIdx.x;
    int t = threadIdx.x, lane = t & 31, h = t >> 5;
    int rb = g_rowptr[n];
    int deg = g_rowptr[n + 1] - rb;

    __shared__ int   s_src[MAXDEG];
    __shared__ float s_w[HH][MAXDEG];
    __shared__ float s_out[HH][DD];

    float2 acc = make_float2(0.f, 0.f);
    const float2* feat2 = (const float2*)g_feat;

    if (deg > 0 && deg <= MAXDEG) {
        float4 er4 = *(const float4*)(g_er + n * HH);
        for (int j = t; j < deg; j += 128) {
            int sn = g_csr[rb + j];
            s_src[j] = sn;
            float4 el4 = *(const float4*)(g_el + sn * HH);
            float e0 = el4.x + er4.x; s_w[0][j] = e0 > 0.f ? e0 : NEG_SLOPE * e0;
            float e1 = el4.y + er4.y; s_w[1][j] = e1 > 0.f ? e1 : NEG_SLOPE * e1;
            float e2 = el4.z + er4.z; s_w[2][j] = e2 > 0.f ? e2 : NEG_SLOPE * e2;
            float e3 = el4.w + er4.w; s_w[3][j] = e3 > 0.f ? e3 : NEG_SLOPE * e3;
        }
        __syncthreads();

        // softmax within warp's own head row
        float m = -1e30f;
        for (int j = lane; j < deg; j += 32) m = fmaxf(m, s_w[h][j]);
        #pragma unroll
        for (int o = 16; o; o >>= 1) m = fmaxf(m, __shfl_xor_sync(0xffffffffu, m, o));
        float s = 0.f;
        for (int j = lane; j < deg; j += 32) {
            float w = __expf(s_w[h][j] - m);
            s_w[h][j] = w;
            s += w;
        }
        #pragma unroll
        for (int o = 16; o; o >>= 1) s += __shfl_xor_sync(0xffffffffu, s, o);
        float inv = 1.0f / s;
        __syncwarp();

        for (int j = 0; j < deg; j++) {
            float w = s_w[h][j];
            float2 f = feat2[(size_t)s_src[j] * 128 + h * 32 + lane];
            acc.x += w * f.x;
            acc.y += w * f.y;
        }
        acc.x *= inv; acc.y *= inv;
    } else if (deg > MAXDEG) {
        // generic fallback (effectively unreachable for Poisson(16) degrees)
        float er_h = g_er[n * HH + h];
        float m = -1e30f;
        for (int j = lane; j < deg; j += 32) {
            int sn = g_csr[rb + j];
            float e = g_el[sn * HH + h] + er_h;
            e = e > 0.f ? e : NEG_SLOPE * e;
            m = fmaxf(m, e);
        }
        #pragma unroll
        for (int o = 16; o; o >>= 1) m = fmaxf(m, __shfl_xor_sync(0xffffffffu, m, o));
        float s = 0.f;
        for (int j = lane; j < deg; j += 32) {
            int sn = g_csr[rb + j];
            float e = g_el[sn * HH + h] + er_h;
            e = e > 0.f ? e : NEG_SLOPE * e;
            s += __expf(e - m);
        }
        #pragma unroll
        for (int o = 16; o; o >>= 1) s += __shfl_xor_sync(0xffffffffu, s, o);
        float inv = 1.0f / s;
        for (int j = 0; j < deg; j++) {
            int sn = g_csr[rb + j];
            float e = g_el[sn * HH + h] + er_h;
            e = e > 0.f ? e : NEG_SLOPE * e;
            float w = __expf(e - m);
            float2 f = feat2[(size_t)sn * 128 + h * 32 + lane];
            acc.x += w * f.x;
            acc.y += w * f.y;
        }
        acc.x *= inv; acc.y *= inv;
    }

    if (MEAN) {
        s_out[h][2 * lane]     = acc.x;
        s_out[h][2 * lane + 1] = acc.y;
        __syncthreads();
        if (t < DD) {
            float v = 0.25f * (s_out[0][t] + s_out[1][t] + s_out[2][t] + s_out[3][t])
                    + 0.25f * (b[t] + b[DD + t] + b[2 * DD + t] + b[3 * DD + t]);
            out[(size_t)n * DD + t] = v;
        }
    } else {
        int o = h * DD + 2 * lane;
        float2 bb = *(const float2*)(b + o);
        float2 r;
        r.x = acc.x + bb.x;
        r.y = acc.y + bb.y;
        *(float2*)(out + (size_t)n * HD + o) = r;
    }
}

// ---------------------------------------------------------------------------
// Final Linear(256->64) + LayerNorm (no affine). 8 nodes per block, 64 threads.
// ---------------------------------------------------------------------------
__global__ void __launch_bounds__(64) final_ln_k(
    const float* __restrict__ hin, const float* __restrict__ Wo,
    const float* __restrict__ bo, float* __restrict__ out)
{
    constexpr int NB = 8;
    __shared__ float sh[NB * HD];     // 8 KB
    __shared__ float so[NB * DD];     // 2 KB
    __shared__ float mu_s[NB], rs_s[NB];
    int t = threadIdx.x;
    int n0 = blockIdx.x * NB;

    for (int idx = t; idx < NB * HD; idx += 64)
        sh[idx] = hin[(size_t)n0 * HD + idx];
    __syncthreads();

    float acc[NB];
    #pragma unroll
    for (int i = 0; i < NB; i++) acc[i] = 0.f;
    float bv = bo[t];

    for (int k = 0; k < HD; k++) {
        float wv = __ldg(&Wo[k * DD + t]);
        #pragma unroll
        for (int i = 0; i < NB; i++) acc[i] += sh[i * HD + k] * wv;
    }

    #pragma unroll
    for (int i = 0; i < NB; i++) so[i * DD + t] = acc[i] + bv;
    __syncthreads();

    if (t < NB) {
        float s = 0.f;
        for (int j = 0; j < DD; j++) s += so[t * DD + j];
        float mu = s * (1.0f / DD);
        float s2 = 0.f;
        for (int j = 0; j < DD; j++) {
            float d = so[t * DD + j] - mu;
            s2 += d * d;
        }
        mu_s[t] = mu;
        rs_s[t] = rsqrtf(s2 * (1.0f / DD) + 1e-5f);
    }
    __syncthreads();

    #pragma unroll
    for (int i = 0; i < NB; i++)
        out[(size_t)(n0 + i) * DD + t] = (so[i * DD + t] - mu_s[i]) * rs_s[i];
}

// ---------------------------------------------------------------------------
// Launch: inputs (metadata order):
// 0 in_feat[N,128] 1 src[E] 2 dst[E] 3 W1[128,256] 4 al1[4,64] 5 ar1[4,64]
// 6 b1[256] 7 Wh[3,64,256] 8 alh[3,4,64] 9 arh[3,4,64] 10 bh[3,256]
// 11 Wo[256,64] 12 bo[64]  -> out float32 [N,64]
// ---------------------------------------------------------------------------
extern "C" void kernel_launch(void* const* d_in, const int* in_sizes, int n_in,
                              void* d_out, int out_size)
{
    const float* in_feat = (const float*)d_in[0];
    const int*   src     = (const int*)d_in[1];
    const int*   dst     = (const int*)d_in[2];
    const float* W1      = (const float*)d_in[3];
    const float* al1     = (const float*)d_in[4];
    const float* ar1     = (const float*)d_in[5];
    const float* b1      = (const float*)d_in[6];
    const float* Wh      = (const float*)d_in[7];
    const float* alh     = (const float*)d_in[8];
    const float* arh     = (const float*)d_in[9];
    const float* bh      = (const float*)d_in[10];
    const float* Wo      = (const float*)d_in[11];
    const float* bo      = (const float*)d_in[12];
    float* out = (float*)d_out;

    float* g_h_ptr;
    float* g_feat_ptr;
    cudaGetSymbolAddress((void**)&g_h_ptr, g_h);
    cudaGetSymbolAddress((void**)&g_feat_ptr, g_feat);

    // CSR build
    zero_cur_k<<<(NN + 255) / 256, 256>>>();
    hist_k<<<(EE + 255) / 256, 256>>>(dst);
    scan_k<<<1, 1024>>>();
    scatter_k<<<(EE + 255) / 256, 256>>>(src, dst);

    const int GB = NN / 8;  // 6250 blocks for node-tiled gemms

    // Layer 1: conv1 (K=128), mean over heads -> g_h[N,64]
    gemm_attn_k<IN_F><<<GB, 256>>>(in_feat, W1, al1, ar1);
    edge_agg_k<true><<<NN, 128>>>(b1, g_h_ptr);

    // Hidden layers 0,1 (mean)
    for (int l = 0; l < 2; l++) {
        gemm_attn_k<DD><<<GB, 256>>>(g_h_ptr, Wh + (size_t)l * DD * HD,
                                     alh + l * HD, arh + l * HD);
        edge_agg_k<true><<<NN, 128>>>(bh + l * HD, g_h_ptr);
    }

    // Hidden layer 2 (full [N,H,D] output)
    gemm_attn_k<DD><<<GB, 256>>>(g_h_ptr, Wh + (size_t)2 * DD * HD,
                                 alh + 2 * HD, arh + 2 * HD);
    edge_agg_k<false><<<NN, 128>>>(bh + 2 * HD, g_h_ptr);

    // Final linear + LayerNorm -> d_out
    final_ln_k<<<GB, 64>>>(g_h_ptr, Wo, bo, out);
}

// round 2
// speedup vs baseline: 1.0999x; 1.0999x over previous
#include <cuda_runtime.h>
#include <cuda_bf16.h>
#include <cstdint>

// Problem constants (match reference_code)
#define NN 50000      // nodes
#define EE 800000     // edges
#define IN_F 128
#define DD 64
#define HH 4
#define HD 256        // H*D
#define NEG_SLOPE 0.2f

// ---------------------------------------------------------------------------
// Scratch (static __device__ arrays — no allocation allowed)
// ---------------------------------------------------------------------------
__device__ float g_feat[(size_t)NN * HD];   // projected features [N,256]
__device__ float g_h[(size_t)NN * HD];      // layer io buffer
__device__ float g_el[(size_t)NN * HH];
__device__ float g_er[(size_t)NN * HH];
__device__ int   g_rowptr[NN + 1];
__device__ int   g_cur[NN];
__device__ int   g_csr[EE];                 // src node per CSR slot (sorted by dst)

// ---------------------------------------------------------------------------
// CSR build: zero -> histogram(dst) -> scan -> scatter
// ---------------------------------------------------------------------------
__global__ void zero_cur_k() {
    int i = blockIdx.x * blockDim.x + threadIdx.x;
    if (i < NN) g_cur[i] = 0;
}

__global__ void hist_k(const int* __restrict__ dst) {
    int e = blockIdx.x * blockDim.x + threadIdx.x;
    if (e < EE) atomicAdd(&g_cur[dst[e]], 1);
}

// single-block exclusive scan over g_cur -> g_rowptr; also re-zeros g_cur
__global__ void scan_k() {
    __shared__ int ws[32];
    __shared__ int s_carry;
    int t = threadIdx.x, lane = t & 31, wid = t >> 5;
    if (t == 0) s_carry = 0;
    __syncthreads();
    for (int base = 0; base < NN; base += 1024) {
        int i = base + t;
        int v = (i < NN) ? g_cur[i] : 0;
        if (i < NN) g_cur[i] = 0;
        int x = v;
        #pragma unroll
        for (int o = 1; o < 32; o <<= 1) {
            int y = __shfl_up_sync(0xffffffffu, x, o);
            if (lane >= o) x += y;
        }
        if (lane == 31) ws[wid] = x;
        __syncthreads();
        if (wid == 0) {
            int y = ws[lane];
            #pragma unroll
            for (int o = 1; o < 32; o <<= 1) {
                int z = __shfl_up_sync(0xffffffffu, y, o);
                if (lane >= o) y += z;
            }
            ws[lane] = y;
        }
        __syncthreads();
        int incl = x + (wid ? ws[wid - 1] : 0);
        int carry = s_carry;
        if (i < NN) g_rowptr[i] = carry + incl - v;
        int total = ws[31];
        __syncthreads();
        if (t == 0) s_carry = carry + total;
        __syncthreads();
    }
    if (t == 0) g_rowptr[NN] = s_carry;
}

__global__ void scatter_k(const int* __restrict__ src, const int* __restrict__ dst) {
    int e = blockIdx.x * blockDim.x + threadIdx.x;
    if (e < EE) {
        int d = dst[e];
        int pos = g_rowptr[d] + atomicAdd(&g_cur[d], 1);
        g_csr[pos] = src[e];
    }
}

// ---------------------------------------------------------------------------
// GEMM + attention coefficients: feat = h @ W  ([N,K]@[K,256]); el/er = feat . al/ar
// 16 nodes per block, 256 threads. LDS.128 shared reads; W via L1-resident LDG.
// Per 4 k-steps: 4 LDG + 16 LDS.128 + 64 FFMA.
// ---------------------------------------------------------------------------
template <int K>
__global__ void __launch_bounds__(256) gemm_attn_k(
    const float* __restrict__ hin, const float* __restrict__ W,
    const float* __restrict__ al, const float* __restrict__ ar)
{
    constexpr int NB = 16;
    constexpr int K4 = K / 4;
    __shared__ float4 sh4[NB * K4];
    __shared__ float red_l[NB][8];
    __shared__ float red_r[NB][8];
    int t = threadIdx.x, lane = t & 31, wid = t >> 5;
    int n0 = blockIdx.x * NB;

    const float4* hin4 = (const float4*)(hin + (size_t)n0 * K);
    for (int idx = t; idx < NB * K4; idx += 256)
        sh4[idx] = hin4[idx];
    __syncthreads();

    float acc[NB];
    #pragma unroll
    for (int i = 0; i < NB; i++) acc[i] = 0.f;

    float a_l = al[t], a_r = ar[t];

    for (int k4 = 0; k4 < K4; k4++) {
        int k = k4 * 4;
        float w0 = __ldg(&W[(k + 0) * HD + t]);
        float w1 = __ldg(&W[(k + 1) * HD + t]);
        float w2 = __ldg(&W[(k + 2) * HD + t]);
        float w3 = __ldg(&W[(k + 3) * HD + t]);
        #pragma unroll
        for (int i = 0; i < NB; i++) {
            float4 s = sh4[i * K4 + k4];
            acc[i] += s.x * w0;
            acc[i] += s.y * w1;
            acc[i] += s.z * w2;
            acc[i] += s.w * w3;
        }
    }

    #pragma unroll
    for (int i = 0; i < NB; i++)
        g_feat[(size_t)(n0 + i) * HD + t] = acc[i];

    // warp-partial el/er reductions, single barrier, then 64-thread combine
    #pragma unroll
    for (int i = 0; i < NB; i++) {
        float pl = acc[i] * a_l;
        float pr = acc[i] * a_r;
        #pragma unroll
        for (int o = 16; o; o >>= 1) {
            pl += __shfl_down_sync(0xffffffffu, pl, o);
            pr += __shfl_down_sync(0xffffffffu, pr, o);
        }
        if (lane == 0) { red_l[i][wid] = pl; red_r[i][wid] = pr; }
    }
    __syncthreads();
    if (t < NB * HH) {
        int i = t >> 2, h = t & 3;   // head h spans warps 2h, 2h+1
        g_el[(n0 + i) * HH + h] = red_l[i][2 * h] + red_l[i][2 * h + 1];
        g_er[(n0 + i) * HH + h] = red_r[i][2 * h] + red_r[i][2 * h + 1];
    }
}

// ---------------------------------------------------------------------------
// Edge softmax + weighted aggregation. One block (128 thr) per dst node,
// warp h handles head h. CSR gather, no atomics, gather loop unrolled x4.
// MAXDEG=64 (Poisson(16) tail; generic fallback for larger).
// ---------------------------------------------------------------------------
template <bool MEAN>
__global__ void __launch_bounds__(128) edge_agg_k(
    const float* __restrict__ b, float* __restrict__ out)
{
    constexpr int MAXDEG = 64;
    int n = blockIdx.x;
    int t = threadIdx.x, lane = t & 31, h = t >> 5;
    int rb = g_rowptr[n];
    int deg = g_rowptr[n + 1] - rb;

    __shared__ int   s_src[MAXDEG];
    __shared__ float s_w[HH][MAXDEG];
    __shared__ float s_out[HH][DD];

    float2 acc = make_float2(0.f, 0.f);
    const float2* fb = (const float2*)g_feat + (h * 32 + lane);

    if (deg > 0 && deg <= MAXDEG) {
        float4 er4 = *(const float4*)(g_er + n * HH);
        if (t < MAXDEG && t < deg) {
            int j = t;
            int sn = g_csr[rb + j];
            s_src[j] = sn;
            float4 el4 = *(const float4*)(g_el + sn * HH);
            float e0 = el4.x + er4.x; s_w[0][j] = e0 > 0.f ? e0 : NEG_SLOPE * e0;
            float e1 = el4.y + er4.y; s_w[1][j] = e1 > 0.f ? e1 : NEG_SLOPE * e1;
            float e2 = el4.z + er4.z; s_w[2][j] = e2 > 0.f ? e2 : NEG_SLOPE * e2;
            float e3 = el4.w + er4.w; s_w[3][j] = e3 > 0.f ? e3 : NEG_SLOPE * e3;
        }
        __syncthreads();

        // softmax within warp's own head row; fold 1/sum into weights
        float m = -1e30f;
        for (int j = lane; j < deg; j += 32) m = fmaxf(m, s_w[h][j]);
        #pragma unroll
        for (int o = 16; o; o >>= 1) m = fmaxf(m, __shfl_xor_sync(0xffffffffu, m, o));
        float s = 0.f;
        for (int j = lane; j < deg; j += 32) {
            float w = __expf(s_w[h][j] - m);
            s_w[h][j] = w;
            s += w;
        }
        #pragma unroll
        for (int o = 16; o; o >>= 1) s += __shfl_xor_sync(0xffffffffu, s, o);
        float inv = 1.0f / s;
        __syncwarp();

        int j = 0;
        for (; j + 4 <= deg; j += 4) {
            int   s0 = s_src[j],     s1 = s_src[j + 1];
            int   s2 = s_src[j + 2], s3 = s_src[j + 3];
            float w0 = s_w[h][j],     w1 = s_w[h][j + 1];
            float w2 = s_w[h][j + 2], w3 = s_w[h][j + 3];
            float2 f0 = fb[(size_t)s0 * 128];
            float2 f1 = fb[(size_t)s1 * 128];
            float2 f2 = fb[(size_t)s2 * 128];
            float2 f3 = fb[(size_t)s3 * 128];
            acc.x += w0 * f0.x; acc.y += w0 * f0.y;
            acc.x += w1 * f1.x; acc.y += w1 * f1.y;
            acc.x += w2 * f2.x; acc.y += w2 * f2.y;
            acc.x += w3 * f3.x; acc.y += w3 * f3.y;
        }
        for (; j < deg; j++) {
            float w = s_w[h][j];
            float2 f = fb[(size_t)s_src[j] * 128];
            acc.x += w * f.x; acc.y += w * f.y;
        }
        acc.x *= inv; acc.y *= inv;
    } else if (deg > MAXDEG) {
        // generic fallback (effectively unreachable for Poisson(16) degrees)
        float er_h = g_er[n * HH + h];
        float m = -1e30f;
        for (int j = lane; j < deg; j += 32) {
            int sn = g_csr[rb + j];
            float e = g_el[sn * HH + h] + er_h;
            e = e > 0.f ? e : NEG_SLOPE * e;
            m = fmaxf(m, e);
        }
        #pragma unroll
        for (int o = 16; o; o >>= 1) m = fmaxf(m, __shfl_xor_sync(0xffffffffu, m, o));
        float s = 0.f;
        for (int j = lane; j < deg; j += 32) {
            int sn = g_csr[rb + j];
            float e = g_el[sn * HH + h] + er_h;
            e = e > 0.f ? e : NEG_SLOPE * e;
            s += __expf(e - m);
        }
        #pragma unroll
        for (int o = 16; o; o >>= 1) s += __shfl_xor_sync(0xffffffffu, s, o);
        float inv = 1.0f / s;
        for (int j = 0; j < deg; j++) {
            int sn = g_csr[rb + j];
            float e = g_el[sn * HH + h] + er_h;
            e = e > 0.f ? e : NEG_SLOPE * e;
            float w = __expf(e - m);
            float2 f = fb[(size_t)sn * 128];
            acc.x += w * f.x; acc.y += w * f.y;
        }
        acc.x *= inv; acc.y *= inv;
    }

    if (MEAN) {
        s_out[h][2 * lane]     = acc.x;
        s_out[h][2 * lane + 1] = acc.y;
        __syncthreads();
        if (t < DD) {
            float v = 0.25f * (s_out[0][t] + s_out[1][t] + s_out[2][t] + s_out[3][t])
                    + 0.25f * (b[t] + b[DD + t] + b[2 * DD + t] + b[3 * DD + t]);
            out[(size_t)n * DD + t] = v;
        }
    } else {
        int o = h * DD + 2 * lane;
        float2 bb = *(const float2*)(b + o);
        float2 r;
        r.x = acc.x + bb.x;
        r.y = acc.y + bb.y;
        *(float2*)(out + (size_t)n * HD + o) = r;
    }
}

// ---------------------------------------------------------------------------
// Final Linear(256->64) + LayerNorm (no affine). 16 nodes/block, 64 threads.
// ---------------------------------------------------------------------------
__global__ void __launch_bounds__(64) final_ln_k(
    const float* __restrict__ hin, const float* __restrict__ Wo,
    const float* __restrict__ bo, float* __restrict__ out)
{
    constexpr int NB = 16;
    constexpr int K4 = HD / 4;               // 64
    __shared__ float4 sh4[NB * K4];          // 16 KB
    __shared__ float so[NB * DD];            // 4 KB
    __shared__ float mu_s[NB], rs_s[NB];
    int t = threadIdx.x;
    int n0 = blockIdx.x * NB;

    const float4* hin4 = (const float4*)(hin + (size_t)n0 * HD);
    for (int idx = t; idx < NB * K4; idx += 64)
        sh4[idx] = hin4[idx];
    __syncthreads();

    float acc[NB];
    #pragma unroll
    for (int i = 0; i < NB; i++) acc[i] = 0.f;
    float bv = bo[t];

    for (int k4 = 0; k4 < K4; k4++) {
        int k = k4 * 4;
        float w0 = __ldg(&Wo[(k + 0) * DD + t]);
        float w1 = __ldg(&Wo[(k + 1) * DD + t]);
        float w2 = __ldg(&Wo[(k + 2) * DD + t]);
        float w3 = __ldg(&Wo[(k + 3) * DD + t]);
        #pragma unroll
        for (int i = 0; i < NB; i++) {
            float4 s = sh4[i * K4 + k4];
            acc[i] += s.x * w0;
            acc[i] += s.y * w1;
            acc[i] += s.z * w2;
            acc[i] += s.w * w3;
        }
    }

    #pragma unroll
    for (int i = 0; i < NB; i++) so[i * DD + t] = acc[i] + bv;
    __syncthreads();

    if (t < NB) {
        float s = 0.f;
        for (int j = 0; j < DD; j++) s += so[t * DD + j];
        float mu = s * (1.0f / DD);
        float s2 = 0.f;
        for (int j = 0; j < DD; j++) {
            float d = so[t * DD + j] - mu;
            s2 += d * d;
        }
        mu_s[t] = mu;
        rs_s[t] = rsqrtf(s2 * (1.0f / DD) + 1e-5f);
    }
    __syncthreads();

    #pragma unroll
    for (int i = 0; i < NB; i++)
        out[(size_t)(n0 + i) * DD + t] = (so[i * DD + t] - mu_s[i]) * rs_s[i];
}

// ---------------------------------------------------------------------------
// Launch: inputs (metadata order):
// 0 in_feat[N,128] 1 src[E] 2 dst[E] 3 W1[128,256] 4 al1[4,64] 5 ar1[4,64]
// 6 b1[256] 7 Wh[3,64,256] 8 alh[3,4,64] 9 arh[3,4,64] 10 bh[3,256]
// 11 Wo[256,64] 12 bo[64]  -> out float32 [N,64]
// ---------------------------------------------------------------------------
extern "C" void kernel_launch(void* const* d_in, const int* in_sizes, int n_in,
                              void* d_out, int out_size)
{
    const float* in_feat = (const float*)d_in[0];
    const int*   src     = (const int*)d_in[1];
    const int*   dst     = (const int*)d_in[2];
    const float* W1      = (const float*)d_in[3];
    const float* al1     = (const float*)d_in[4];
    const float* ar1     = (const float*)d_in[5];
    const float* b1      = (const float*)d_in[6];
    const float* Wh      = (const float*)d_in[7];
    const float* alh     = (const float*)d_in[8];
    const float* arh     = (const float*)d_in[9];
    const float* bh      = (const float*)d_in[10];
    const float* Wo      = (const float*)d_in[11];
    const float* bo      = (const float*)d_in[12];
    float* out = (float*)d_out;

    float* g_h_ptr;
    cudaGetSymbolAddress((void**)&g_h_ptr, g_h);

    // CSR build
    zero_cur_k<<<(NN + 255) / 256, 256>>>();
    hist_k<<<(EE + 255) / 256, 256>>>(dst);
    scan_k<<<1, 1024>>>();
    scatter_k<<<(EE + 255) / 256, 256>>>(src, dst);

    const int GB = NN / 16;  // 3125 blocks for node-tiled gemms

    // Layer 1: conv1 (K=128), mean over heads -> g_h[N,64]
    gemm_attn_k<IN_F><<<GB, 256>>>(in_feat, W1, al1, ar1);
    edge_agg_k<true><<<NN, 128>>>(b1, g_h_ptr);

    // Hidden layers 0,1 (mean)
    for (int l = 0; l < 2; l++) {
        gemm_attn_k<DD><<<GB, 256>>>(g_h_ptr, Wh + (size_t)l * DD * HD,
                                     alh + l * HD, arh + l * HD);
        edge_agg_k<true><<<NN, 128>>>(bh + l * HD, g_h_ptr);
    }

    // Hidden layer 2 (full [N,H,D] output)
    gemm_attn_k<DD><<<GB, 256>>>(g_h_ptr, Wh + (size_t)2 * DD * HD,
                                 alh + 2 * HD, arh + 2 * HD);
    edge_agg_k<false><<<NN, 128>>>(bh + 2 * HD, g_h_ptr);

    // Final linear + LayerNorm -> d_out
    final_ln_k<<<GB, 64>>>(g_h_ptr, Wo, bo, out);
}

// round 3
// speedup vs baseline: 1.2873x; 1.1704x over previous
#include <cuda_runtime.h>
#include <cuda_bf16.h>
#include <cstdint>

// Problem constants (match reference_code)
#define NN 50000      // nodes
#define EE 800000     // edges
#define IN_F 128
#define DD 64
#define HH 4
#define HD 256        // H*D
#define NEG_SLOPE 0.2f

// ---------------------------------------------------------------------------
// Scratch (static __device__ arrays — no allocation allowed)
// ---------------------------------------------------------------------------
__device__ float g_feat[(size_t)NN * HD];   // projected features [N,256]
__device__ float g_h[(size_t)NN * HD];      // layer io buffer
__device__ float g_el[(size_t)NN * HH];
__device__ float g_er[(size_t)NN * HH];
__device__ int   g_rowptr[NN + 1];
__device__ int   g_cur[NN];
__device__ int   g_csr[EE];                 // src node per CSR slot (sorted by dst)
__device__ float g_Wh[IN_F * HD];           // tf32-high split of current layer W
__device__ float g_Wl[IN_F * HD];           // tf32-low  split of current layer W

// ---------------------------------------------------------------------------
// CSR build: zero -> histogram(dst) -> scan -> scatter
// ---------------------------------------------------------------------------
__global__ void zero_cur_k() {
    int i = blockIdx.x * blockDim.x + threadIdx.x;
    if (i < NN) g_cur[i] = 0;
}

__global__ void hist_k(const int* __restrict__ dst) {
    int e = blockIdx.x * blockDim.x + threadIdx.x;
    if (e < EE) atomicAdd(&g_cur[dst[e]], 1);
}

// single-block exclusive scan over g_cur -> g_rowptr; also re-zeros g_cur
__global__ void scan_k() {
    __shared__ int ws[32];
    __shared__ int s_carry;
    int t = threadIdx.x, lane = t & 31, wid = t >> 5;
    if (t == 0) s_carry = 0;
    __syncthreads();
    for (int base = 0; base < NN; base += 1024) {
        int i = base + t;
        int v = (i < NN) ? g_cur[i] : 0;
        if (i < NN) g_cur[i] = 0;
        int x = v;
        #pragma unroll
        for (int o = 1; o < 32; o <<= 1) {
            int y = __shfl_up_sync(0xffffffffu, x, o);
            if (lane >= o) x += y;
        }
        if (lane == 31) ws[wid] = x;
        __syncthreads();
        if (wid == 0) {
            int y = ws[lane];
            #pragma unroll
            for (int o = 1; o < 32; o <<= 1) {
                int z = __shfl_up_sync(0xffffffffu, y, o);
                if (lane >= o) y += z;
            }
            ws[lane] = y;
        }
        __syncthreads();
        int incl = x + (wid ? ws[wid - 1] : 0);
        int carry = s_carry;
        if (i < NN) g_rowptr[i] = carry + incl - v;
        int total = ws[31];
        __syncthreads();
        if (t == 0) s_carry = carry + total;
        __syncthreads();
    }
    if (t == 0) g_rowptr[NN] = s_carry;
}

__global__ void scatter_k(const int* __restrict__ src, const int* __restrict__ dst) {
    int e = blockIdx.x * blockDim.x + threadIdx.x;
    if (e < EE) {
        int d = dst[e];
        int pos = g_rowptr[d] + atomicAdd(&g_cur[d], 1);
        g_csr[pos] = src[e];
    }
}

// ---------------------------------------------------------------------------
// Weight split: W = Wh + Wl, both tf32 (rna). Kills weight rounding error.
// ---------------------------------------------------------------------------
__global__ void split_w_k(const float* __restrict__ W, int n) {
    int i = blockIdx.x * blockDim.x + threadIdx.x;
    if (i < n) {
        float w = W[i];
        uint32_t hb;
        asm("cvt.rna.tf32.f32 %0, %1;" : "=r"(hb) : "f"(w));
        float wh = __uint_as_float(hb);
        float r = w - wh;
        uint32_t lb;
        asm("cvt.rna.tf32.f32 %0, %1;" : "=r"(lb) : "f"(r));
        g_Wh[i] = wh;
        g_Wl[i] = __uint_as_float(lb);
    }
}

// ---------------------------------------------------------------------------
// tf32 tensor-core GEMM + fused attention coefficients.
// feat[64 x 256] = A[64 x K] @ (Wh+Wl)[K x 256], el/er epilogue.
// Block: 256 thr = 8 warps, 2(M) x 4(N); warp tile m32 x n64 (1 head/warp).
// ---------------------------------------------------------------------------
__device__ __forceinline__ void mma_tf32(float* c, const uint32_t* a,
                                         uint32_t b0, uint32_t b1)
{
    asm volatile(
        "mma.sync.aligned.m16n8k8.row.col.f32.tf32.tf32.f32 "
        "{%0,%1,%2,%3}, {%4,%5,%6,%7}, {%8,%9}, {%0,%1,%2,%3};"
        : "+f"(c[0]), "+f"(c[1]), "+f"(c[2]), "+f"(c[3])
        : "r"(a[0]), "r"(a[1]), "r"(a[2]), "r"(a[3]), "r"(b0), "r"(b1));
}

template <int K>
__global__ void __launch_bounds__(256) gemm_mma_k(
    const float* __restrict__ hin,
    const float* __restrict__ al, const float* __restrict__ ar)
{
    constexpr int AS = K + 4;    // A smem stride (bank ≡ (4r+c)%32, conflict-free)
    constexpr int WS = 264;      // W smem stride (bank ≡ (8k+n)%32, conflict-free)
    constexpr int NCH = K / 32;  // 32-wide k-chunks
    extern __shared__ float sm[];
    float* sA  = sm;                 // 64*AS
    float* sWh = sm + 64 * AS;       // 32*WS
    float* sWl = sWh + 32 * WS;      // 32*WS

    int t = threadIdx.x, lane = t & 31, wid = t >> 5;
    int wm = wid >> 2, wn = wid & 3;     // warp M-row, warp N-col (= head)
    int g = lane >> 2, q = lane & 3;     // groupID (row), quad lane (col)
    int n0 = blockIdx.x * 64;

    // Stage A, tf32-rounded, zero-fill rows >= NN
    for (int idx = t; idx < 64 * K; idx += 256) {
        int r = idx / K, c = idx % K;
        float v = 0.f;
        if (n0 + r < NN) v = hin[(size_t)(n0 + r) * K + c];
        uint32_t vb;
        asm("cvt.rna.tf32.f32 %0, %1;" : "=r"(vb) : "f"(v));
        sA[r * AS + c] = __uint_as_float(vb);
    }

    float c_[2][8][4];
    #pragma unroll
    for (int i = 0; i < 2; i++)
        #pragma unroll
        for (int j = 0; j < 8; j++)
            #pragma unroll
            for (int r = 0; r < 4; r++) c_[i][j][r] = 0.f;

    for (int kc = 0; kc < NCH; kc++) {
        __syncthreads();
        // stage Wh/Wl chunk [32 x 256]
        for (int idx = t; idx < 32 * 256; idx += 256) {
            int kk = idx >> 8, n = idx & 255;
            sWh[kk * WS + n] = g_Wh[(kc * 32 + kk) * 256 + n];
            sWl[kk * WS + n] = g_Wl[(kc * 32 + kk) * 256 + n];
        }
        __syncthreads();

        #pragma unroll
        for (int j8 = 0; j8 < 4; j8++) {
            int kcol = kc * 32 + j8 * 8;
            uint32_t a[2][4];
            #pragma unroll
            for (int i = 0; i < 2; i++) {
                int r = wm * 32 + i * 16 + g;
                a[i][0] = __float_as_uint(sA[r * AS + kcol + q]);
                a[i][1] = __float_as_uint(sA[(r + 8) * AS + kcol + q]);
                a[i][2] = __float_as_uint(sA[r * AS + kcol + q + 4]);
                a[i][3] = __float_as_uint(sA[(r + 8) * AS + kcol + q + 4]);
            }
            #pragma unroll
            for (int j = 0; j < 8; j++) {
                int ncol = wn * 64 + j * 8 + g;
                int krow = j8 * 8 + q;
                uint32_t bh0 = __float_as_uint(sWh[krow * WS + ncol]);
                uint32_t bh1 = __float_as_uint(sWh[(krow + 4) * WS + ncol]);
                uint32_t bl0 = __float_as_uint(sWl[krow * WS + ncol]);
                uint32_t bl1 = __float_as_uint(sWl[(krow + 4) * WS + ncol]);
                #pragma unroll
                for (int i = 0; i < 2; i++) {
                    mma_tf32(c_[i][j], a[i], bh0, bh1);
                    mma_tf32(c_[i][j], a[i], bl0, bl1);
                }
            }
        }
    }

    // Epilogue: store feat, fused el/er (this warp's head = wn)
    float alv[8][2], arv[8][2];
    #pragma unroll
    for (int j = 0; j < 8; j++) {
        int col = wn * 64 + j * 8 + 2 * q;
        alv[j][0] = al[col]; alv[j][1] = al[col + 1];
        arv[j][0] = ar[col]; arv[j][1] = ar[col + 1];
    }
    #pragma unroll
    for (int i = 0; i < 2; i++) {
        int rtop = n0 + wm * 32 + i * 16 + g;
        int rbot = rtop + 8;
        float plt = 0.f, prt = 0.f, plb = 0.f, prb = 0.f;
        #pragma unroll
        for (int j = 0; j < 8; j++) {
            int cb = wn * 64 + j * 8 + 2 * q;
            if (rtop < NN)
                *(float2*)&g_feat[(size_t)rtop * HD + cb] =
                    make_float2(c_[i][j][0], c_[i][j][1]);
            if (rbot < NN)
                *(float2*)&g_feat[(size_t)rbot * HD + cb] =
                    make_float2(c_[i][j][2], c_[i][j][3]);
            plt += c_[i][j][0] * alv[j][0] + c_[i][j][1] * alv[j][1];
            prt += c_[i][j][0] * arv[j][0] + c_[i][j][1] * arv[j][1];
            plb += c_[i][j][2] * alv[j][0] + c_[i][j][3] * alv[j][1];
            prb += c_[i][j][2] * arv[j][0] + c_[i][j][3] * arv[j][1];
        }
        #pragma unroll
        for (int o = 1; o <= 2; o <<= 1) {
            plt += __shfl_xor_sync(0xffffffffu, plt, o);
            prt += __shfl_xor_sync(0xffffffffu, prt, o);
            plb += __shfl_xor_sync(0xffffffffu, plb, o);
            prb += __shfl_xor_sync(0xffffffffu, prb, o);
        }
        if (q == 0) {
            if (rtop < NN) { g_el[rtop * HH + wn] = plt; g_er[rtop * HH + wn] = prt; }
            if (rbot < NN) { g_el[rbot * HH + wn] = plb; g_er[rbot * HH + wn] = prb; }
        }
    }
}

// ---------------------------------------------------------------------------
// Edge softmax + weighted aggregation. One block (128 thr) per dst node,
// warp h handles head h. CSR gather, no atomics, gather loop unrolled x4.
// ---------------------------------------------------------------------------
template <bool MEAN>
__global__ void __launch_bounds__(128) edge_agg_k(
    const float* __restrict__ b, float* __restrict__ out)
{
    constexpr int MAXDEG = 64;
    int n = blockIdx.x;
    int t = threadIdx.x, lane = t & 31, h = t >> 5;
    int rb = g_rowptr[n];
    int deg = g_rowptr[n + 1] - rb;

    __shared__ int   s_src[MAXDEG];
    __shared__ float s_w[HH][MAXDEG];
    __shared__ float s_out[HH][DD];

    float2 acc = make_float2(0.f, 0.f);
    const float2* fb = (const float2*)g_feat + (h * 32 + lane);

    if (deg > 0 && deg <= MAXDEG) {
        float4 er4 = *(const float4*)(g_er + n * HH);
        if (t < MAXDEG && t < deg) {
            int j = t;
            int sn = g_csr[rb + j];
            s_src[j] = sn;
            float4 el4 = *(const float4*)(g_el + sn * HH);
            float e0 = el4.x + er4.x; s_w[0][j] = e0 > 0.f ? e0 : NEG_SLOPE * e0;
            float e1 = el4.y + er4.y; s_w[1][j] = e1 > 0.f ? e1 : NEG_SLOPE * e1;
            float e2 = el4.z + er4.z; s_w[2][j] = e2 > 0.f ? e2 : NEG_SLOPE * e2;
            float e3 = el4.w + er4.w; s_w[3][j] = e3 > 0.f ? e3 : NEG_SLOPE * e3;
        }
        __syncthreads();

        float m = -1e30f;
        for (int j = lane; j < deg; j += 32) m = fmaxf(m, s_w[h][j]);
        #pragma unroll
        for (int o = 16; o; o >>= 1) m = fmaxf(m, __shfl_xor_sync(0xffffffffu, m, o));
        float s = 0.f;
        for (int j = lane; j < deg; j += 32) {
            float w = __expf(s_w[h][j] - m);
            s_w[h][j] = w;
            s += w;
        }
        #pragma unroll
        for (int o = 16; o; o >>= 1) s += __shfl_xor_sync(0xffffffffu, s, o);
        float inv = 1.0f / s;
        __syncwarp();

        int j = 0;
        for (; j + 4 <= deg; j += 4) {
            int   s0 = s_src[j],     s1 = s_src[j + 1];
            int   s2 = s_src[j + 2], s3 = s_src[j + 3];
            float w0 = s_w[h][j],     w1 = s_w[h][j + 1];
            float w2 = s_w[h][j + 2], w3 = s_w[h][j + 3];
            float2 f0 = fb[(size_t)s0 * 128];
            float2 f1 = fb[(size_t)s1 * 128];
            float2 f2 = fb[(size_t)s2 * 128];
            float2 f3 = fb[(size_t)s3 * 128];
            acc.x += w0 * f0.x; acc.y += w0 * f0.y;
            acc.x += w1 * f1.x; acc.y += w1 * f1.y;
            acc.x += w2 * f2.x; acc.y += w2 * f2.y;
            acc.x += w3 * f3.x; acc.y += w3 * f3.y;
        }
        for (; j < deg; j++) {
            float w = s_w[h][j];
            float2 f = fb[(size_t)s_src[j] * 128];
            acc.x += w * f.x; acc.y += w * f.y;
        }
        acc.x *= inv; acc.y *= inv;
    } else if (deg > MAXDEG) {
        float er_h = g_er[n * HH + h];
        float m = -1e30f;
        for (int j = lane; j < deg; j += 32) {
            int sn = g_csr[rb + j];
            float e = g_el[sn * HH + h] + er_h;
            e = e > 0.f ? e : NEG_SLOPE * e;
            m = fmaxf(m, e);
        }
        #pragma unroll
        for (int o = 16; o; o >>= 1) m = fmaxf(m, __shfl_xor_sync(0xffffffffu, m, o));
        float s = 0.f;
        for (int j = lane; j < deg; j += 32) {
            int sn = g_csr[rb + j];
            float e = g_el[sn * HH + h] + er_h;
            e = e > 0.f ? e : NEG_SLOPE * e;
            s += __expf(e - m);
        }
        #pragma unroll
        for (int o = 16; o; o >>= 1) s += __shfl_xor_sync(0xffffffffu, s, o);
        float inv = 1.0f / s;
        for (int j = 0; j < deg; j++) {
            int sn = g_csr[rb + j];
            float e = g_el[sn * HH + h] + er_h;
            e = e > 0.f ? e : NEG_SLOPE * e;
            float w = __expf(e - m);
            float2 f = fb[(size_t)sn * 128];
            acc.x += w * f.x; acc.y += w * f.y;
        }
        acc.x *= inv; acc.y *= inv;
    }

    if (MEAN) {
        s_out[h][2 * lane]     = acc.x;
        s_out[h][2 * lane + 1] = acc.y;
        __syncthreads();
        if (t < DD) {
            float v = 0.25f * (s_out[0][t] + s_out[1][t] + s_out[2][t] + s_out[3][t])
                    + 0.25f * (b[t] + b[DD + t] + b[2 * DD + t] + b[3 * DD + t]);
            out[(size_t)n * DD + t] = v;
        }
    } else {
        int o = h * DD + 2 * lane;
        float2 bb = *(const float2*)(b + o);
        float2 r;
        r.x = acc.x + bb.x;
        r.y = acc.y + bb.y;
        *(float2*)(out + (size_t)n * HD + o) = r;
    }
}

// ---------------------------------------------------------------------------
// Final Linear(256->64) + LayerNorm (no affine). 16 nodes/block, 64 threads.
// ---------------------------------------------------------------------------
__global__ void __launch_bounds__(64) final_ln_k(
    const float* __restrict__ hin, const float* __restrict__ Wo,
    const float* __restrict__ bo, float* __restrict__ out)
{
    constexpr int NB = 16;
    constexpr int K4 = HD / 4;               // 64
    __shared__ float4 sh4[NB * K4];          // 16 KB
    __shared__ float so[NB * DD];            // 4 KB
    __shared__ float mu_s[NB], rs_s[NB];
    int t = threadIdx.x;
    int n0 = blockIdx.x * NB;

    const float4* hin4 = (const float4*)(hin + (size_t)n0 * HD);
    for (int idx = t; idx < NB * K4; idx += 64)
        sh4[idx] = hin4[idx];
    __syncthreads();

    float acc[NB];
    #pragma unroll
    for (int i = 0; i < NB; i++) acc[i] = 0.f;
    float bv = bo[t];

    for (int k4 = 0; k4 < K4; k4++) {
        int k = k4 * 4;
        float w0 = __ldg(&Wo[(k + 0) * DD + t]);
        float w1 = __ldg(&Wo[(k + 1) * DD + t]);
        float w2 = __ldg(&Wo[(k + 2) * DD + t]);
        float w3 = __ldg(&Wo[(k + 3) * DD + t]);
        #pragma unroll
        for (int i = 0; i < NB; i++) {
            float4 s = sh4[i * K4 + k4];
            acc[i] += s.x * w0;
            acc[i] += s.y * w1;
            acc[i] += s.z * w2;
            acc[i] += s.w * w3;
        }
    }

    #pragma unroll
    for (int i = 0; i < NB; i++) so[i * DD + t] = acc[i] + bv;
    __syncthreads();

    if (t < NB) {
        float s = 0.f;
        for (int j = 0; j < DD; j++) s += so[t * DD + j];
        float mu = s * (1.0f / DD);
        float s2 = 0.f;
        for (int j = 0; j < DD; j++) {
            float d = so[t * DD + j] - mu;
            s2 += d * d;
        }
        mu_s[t] = mu;
        rs_s[t] = rsqrtf(s2 * (1.0f / DD) + 1e-5f);
    }
    __syncthreads();

    #pragma unroll
    for (int i = 0; i < NB; i++)
        out[(size_t)(n0 + i) * DD + t] = (so[i * DD + t] - mu_s[i]) * rs_s[i];
}

// ---------------------------------------------------------------------------
// Launch: inputs (metadata order):
// 0 in_feat[N,128] 1 src[E] 2 dst[E] 3 W1[128,256] 4 al1[4,64] 5 ar1[4,64]
// 6 b1[256] 7 Wh[3,64,256] 8 alh[3,4,64] 9 arh[3,4,64] 10 bh[3,256]
// 11 Wo[256,64] 12 bo[64]  -> out float32 [N,64]
// ---------------------------------------------------------------------------
extern "C" void kernel_launch(void* const* d_in, const int* in_sizes, int n_in,
                              void* d_out, int out_size)
{
    const float* in_feat = (const float*)d_in[0];
    const int*   src     = (const int*)d_in[1];
    const int*   dst     = (const int*)d_in[2];
    const float* W1      = (const float*)d_in[3];
    const float* al1     = (const float*)d_in[4];
    const float* ar1     = (const float*)d_in[5];
    const float* b1      = (const float*)d_in[6];
    const float* Whp     = (const float*)d_in[7];
    const float* alh     = (const float*)d_in[8];
    const float* arh     = (const float*)d_in[9];
    const float* bh      = (const float*)d_in[10];
    const float* Wo      = (const float*)d_in[11];
    const float* bo      = (const float*)d_in[12];
    float* out = (float*)d_out;

    float* g_h_ptr;
    cudaGetSymbolAddress((void**)&g_h_ptr, g_h);

    const int SMEM1 = (64 * (IN_F + 4) + 2 * 32 * 264) * 4;   // 101376 B
    const int SMEMH = (64 * (DD + 4) + 2 * 32 * 264) * 4;     //  84992 B
    cudaFuncSetAttribute(gemm_mma_k<IN_F>,
                         cudaFuncAttributeMaxDynamicSharedMemorySize, SMEM1);
    cudaFuncSetAttribute(gemm_mma_k<DD>,
                         cudaFuncAttributeMaxDynamicSharedMemorySize, SMEMH);

    // CSR build
    zero_cur_k<<<(NN + 255) / 256, 256>>>();
    hist_k<<<(EE + 255) / 256, 256>>>(dst);
    scan_k<<<1, 1024>>>();
    scatter_k<<<(EE + 255) / 256, 256>>>(src, dst);

    const int GMMA = (NN + 63) / 64;   // 782 blocks

    // Layer 1: conv1 (K=128), mean over heads -> g_h[N,64]
    split_w_k<<<(IN_F * HD + 255) / 256, 256>>>(W1, IN_F * HD);
    gemm_mma_k<IN_F><<<GMMA, 256, SMEM1>>>(in_feat, al1, ar1);
    edge_agg_k<true><<<NN, 128>>>(b1, g_h_ptr);

    // Hidden layers 0,1 (mean)
    for (int l = 0; l < 2; l++) {
        split_w_k<<<(DD * HD + 255) / 256, 256>>>(Whp + (size_t)l * DD * HD, DD * HD);
        gemm_mma_k<DD><<<GMMA, 256, SMEMH>>>(g_h_ptr, alh + l * HD, arh + l * HD);
        edge_agg_k<true><<<NN, 128>>>(bh + l * HD, g_h_ptr);
    }

    // Hidden layer 2 (full [N,H,D] output)
    split_w_k<<<(DD * HD + 255) / 256, 256>>>(Whp + (size_t)2 * DD * HD, DD * HD);
    gemm_mma_k<DD><<<GMMA, 256, SMEMH>>>(g_h_ptr, alh + 2 * HD, arh + 2 * HD);
    edge_agg_k<false><<<NN, 128>>>(bh + 2 * HD, g_h_ptr);

    // Final linear + LayerNorm -> d_out
    final_ln_k<<<NN / 16, 64>>>(g_h_ptr, Wo, bo, out);
}